// round 1
// baseline (speedup 1.0000x reference)
#include <cuda_runtime.h>
#include <cuda_bf16.h>
#include <math.h>

// Problem constants
#define BSZ 16
#define TT  500
#define EE  1024
#define VV  4000
#define LL  100
#define SS  201          // 2L+1
#define GG  101          // gathered columns per (b,t): blank + L labels
#define MM  (BSZ*TT)     // 8000 rows
#define NEGF (-1e30f)

// Scratch (device globals: allocation-free per harness rules)
__device__ float g_logits[(size_t)MM * VV];   // 128 MB
__device__ float g_lp[(size_t)MM * GG];       // 3.23 MB
__device__ float g_ll[BSZ];

// ---------------------------------------------------------------------------
// Kernel 1: logits = hs @ W + b   (fp32 SIMT tiled GEMM)
// A = hs [M=8000, K=1024] row-major, B = W [K=1024, N=4000] row-major
// ---------------------------------------------------------------------------
#define BM 128
#define BN 128
#define BK 16
#define TM 8
#define TN 8
#define LDP 132   // padded leading dim for smem tiles (16B-aligned, conflict-reducing)

__global__ __launch_bounds__(256, 1)
void gemm_bias_kernel(const float* __restrict__ A, const float* __restrict__ B,
                      const float* __restrict__ bias) {
    __shared__ float As[BK][LDP];
    __shared__ float Bs[BK][LDP];

    const int bx = blockIdx.x;           // N tiles: 32
    const int by = blockIdx.y;           // M tiles: 63
    const int row0 = by * BM;
    const int col0 = bx * BN;
    const int tid = threadIdx.x;
    const int tx = tid & 15;             // 0..15 -> N
    const int ty = tid >> 4;             // 0..15 -> M

    float acc[TM][TN];
#pragma unroll
    for (int r = 0; r < TM; r++)
#pragma unroll
        for (int c = 0; c < TN; c++) acc[r][c] = 0.0f;

    for (int k0 = 0; k0 < EE; k0 += BK) {
        // Load A tile: 128 rows x 16 k, transposed into As[k][m]
#pragma unroll
        for (int i = 0; i < 2; i++) {
            int f = tid + i * 256;       // 0..511
            int r = f >> 2;              // row within tile 0..127
            int c4 = f & 3;              // which float4 along K
            int grow = row0 + r;
            float4 v = make_float4(0.f, 0.f, 0.f, 0.f);
            if (grow < MM)
                v = *(const float4*)(A + (size_t)grow * EE + k0 + c4 * 4);
            As[c4 * 4 + 0][r] = v.x;
            As[c4 * 4 + 1][r] = v.y;
            As[c4 * 4 + 2][r] = v.z;
            As[c4 * 4 + 3][r] = v.w;
        }
        // Load B tile: 16 k-rows x 128 cols, direct
#pragma unroll
        for (int i = 0; i < 2; i++) {
            int f = tid + i * 256;       // 0..511
            int kr = f >> 5;             // 0..15
            int n4 = f & 31;             // float4 index along N
            int gcol = col0 + n4 * 4;
            float4 v = make_float4(0.f, 0.f, 0.f, 0.f);
            if (gcol < VV)               // VV%4==0 -> float4 fully in or out
                v = *(const float4*)(B + (size_t)(k0 + kr) * VV + gcol);
            *(float4*)&Bs[kr][n4 * 4] = v;
        }
        __syncthreads();

#pragma unroll
        for (int kk = 0; kk < BK; kk++) {
            float ra[TM], rb[TN];
            *(float4*)&ra[0] = *(const float4*)&As[kk][ty * TM + 0];
            *(float4*)&ra[4] = *(const float4*)&As[kk][ty * TM + 4];
            *(float4*)&rb[0] = *(const float4*)&Bs[kk][tx * TN + 0];
            *(float4*)&rb[4] = *(const float4*)&Bs[kk][tx * TN + 4];
#pragma unroll
            for (int r = 0; r < TM; r++)
#pragma unroll
                for (int c = 0; c < TN; c++)
                    acc[r][c] = fmaf(ra[r], rb[c], acc[r][c]);
        }
        __syncthreads();
    }

    // Store with bias
    float bv[TN];
#pragma unroll
    for (int c4 = 0; c4 < TN; c4 += 4) {
        int gcol = col0 + tx * TN + c4;
        float4 v = make_float4(0.f, 0.f, 0.f, 0.f);
        if (gcol < VV) v = *(const float4*)(bias + gcol);
        bv[c4 + 0] = v.x; bv[c4 + 1] = v.y; bv[c4 + 2] = v.z; bv[c4 + 3] = v.w;
    }
#pragma unroll
    for (int r = 0; r < TM; r++) {
        int grow = row0 + ty * TM + r;
        if (grow >= MM) continue;
#pragma unroll
        for (int c4 = 0; c4 < TN; c4 += 4) {
            int gcol = col0 + tx * TN + c4;
            if (gcol < VV) {
                float4 v;
                v.x = acc[r][c4 + 0] + bv[c4 + 0];
                v.y = acc[r][c4 + 1] + bv[c4 + 1];
                v.z = acc[r][c4 + 2] + bv[c4 + 2];
                v.w = acc[r][c4 + 3] + bv[c4 + 3];
                *(float4*)(g_logits + (size_t)grow * VV + gcol) = v;
            }
        }
    }
}

// ---------------------------------------------------------------------------
// Kernel 2: per-row logsumexp over V, then gather lp at blank + labels
// ---------------------------------------------------------------------------
__global__ __launch_bounds__(256)
void lse_gather_kernel(const int* __restrict__ ys) {
    const int row = blockIdx.x;          // b*TT + t
    const int b = row / TT;
    const float* lr = g_logits + (size_t)row * VV;
    __shared__ float red[256];
    const int tid = threadIdx.x;

    float m = NEGF;
    for (int v = tid; v < VV; v += 256) m = fmaxf(m, lr[v]);
    red[tid] = m;
    __syncthreads();
    for (int s = 128; s > 0; s >>= 1) {
        if (tid < s) red[tid] = fmaxf(red[tid], red[tid + s]);
        __syncthreads();
    }
    const float mx = red[0];
    __syncthreads();

    float sum = 0.0f;
    for (int v = tid; v < VV; v += 256) sum += expf(lr[v] - mx);
    red[tid] = sum;
    __syncthreads();
    for (int s = 128; s > 0; s >>= 1) {
        if (tid < s) red[tid] += red[tid + s];
        __syncthreads();
    }
    const float lse = mx + logf(red[0]);

    if (tid < GG) {
        int col = 0;
        if (tid > 0) {
            int y = ys[b * LL + (tid - 1)];
            col = y < 0 ? 0 : y;         // padded labels -> blank
        }
        g_lp[(size_t)row * GG + tid] = lr[col] - lse;
    }
}

// ---------------------------------------------------------------------------
// Kernel 3: CTC forward DP, one block per batch element.
// lp for the whole sequence staged in dynamic shared memory (~200 KB).
// ---------------------------------------------------------------------------
__global__ __launch_bounds__(256)
void ctc_dp_kernel(const int* __restrict__ ys, const int* __restrict__ ilens,
                   const int* __restrict__ olens) {
    extern __shared__ float sm[];
    float* lps = sm;                     // [TT][GG]
    float* abuf = sm + TT * GG;          // [2][256]

    const int b = blockIdx.x;
    const int tid = threadIdx.x;
    const int s = tid;                   // state index, active when s < SS

    // Stage lp[b] into shared
    const float* src = g_lp + (size_t)b * TT * GG;
    for (int i = tid; i < TT * GG; i += blockDim.x) lps[i] = src[i];

    // Per-state metadata
    int g = 0;
    bool allow = false;
    if (s < SS && (s & 1)) {
        int l = s >> 1;
        g = 1 + l;
        int yr = ys[b * LL + l];
        int y = yr < 0 ? 0 : yr;
        int ypr = -1;
        if (l > 0) {
            int yp = ys[b * LL + l - 1];
            ypr = yp < 0 ? 0 : yp;
        }
        allow = (y != 0) && (y != ypr);
    }

    float* a0 = abuf;
    float* a1 = abuf + 256;
    if (s < 256)
        a0[s] = (s == 0) ? lps[0] : ((s == 1) ? lps[1] : NEGF);
    __syncthreads();

    const int ilen = ilens[b];
    for (int t = 1; t < ilen; t++) {
        if (s < SS) {
            float v1 = a0[s];
            float v2 = (s >= 1) ? a0[s - 1] : NEGF;
            float v3 = (s >= 2 && allow) ? a0[s - 2] : NEGF;
            float m = fmaxf(v1, fmaxf(v2, v3));
            float sum = expf(v1 - m) + expf(v2 - m) + expf(v3 - m);
            a1[s] = m + logf(sum) + lps[t * GG + g];
        }
        __syncthreads();
        float* tmp = a0; a0 = a1; a1 = tmp;
    }

    if (tid == 0) {
        const int olen = olens[b];
        float va = a0[2 * olen];
        float vb = a0[2 * olen - 1];
        float m = fmaxf(va, vb);
        g_ll[b] = m + logf(expf(va - m) + expf(vb - m));
    }
}

// ---------------------------------------------------------------------------
// Kernel 4: loss = -mean(ll)
// ---------------------------------------------------------------------------
__global__ void finalize_kernel(float* __restrict__ out) {
    if (threadIdx.x == 0) {
        float sum = 0.0f;
        for (int i = 0; i < BSZ; i++) sum += g_ll[i];
        out[0] = -sum / (float)BSZ;
    }
}

// ---------------------------------------------------------------------------
extern "C" void kernel_launch(void* const* d_in, const int* in_sizes, int n_in,
                              void* d_out, int out_size) {
    const float* hs    = (const float*)d_in[0];
    const float* W     = (const float*)d_in[1];
    const float* bias  = (const float*)d_in[2];
    const int*   ys    = (const int*)d_in[3];
    const int*   ilens = (const int*)d_in[4];
    const int*   olens = (const int*)d_in[5];
    float* out = (float*)d_out;

    dim3 ggrid((VV + BN - 1) / BN, (MM + BM - 1) / BM);   // 32 x 63
    gemm_bias_kernel<<<ggrid, 256>>>(hs, W, bias);

    lse_gather_kernel<<<MM, 256>>>(ys);

    const int dp_smem = TT * GG * sizeof(float) + 2 * 256 * sizeof(float);
    cudaFuncSetAttribute(ctc_dp_kernel,
                         cudaFuncAttributeMaxDynamicSharedMemorySize, dp_smem);
    ctc_dp_kernel<<<BSZ, 256, dp_smem>>>(ys, ilens, olens);

    finalize_kernel<<<1, 32>>>(out);
}

// round 3
// speedup vs baseline: 2.4028x; 2.4028x over previous
#include <cuda_runtime.h>
#include <cuda_bf16.h>
#include <math.h>
#include <stdint.h>

// Problem constants
#define BSZ 16
#define TT  500
#define EE  1024
#define VV  4000
#define LL  100
#define SS  201
#define GG  101
#define MM  (BSZ*TT)     // 8000
#define MPAD 8064        // 63*128
#define NPAD 4096        // 32*128
#define NEGF (-1e30f)

// GEMM tiling
#define BM 128
#define BN 128
#define BK 32
#define NST 4
#define KITERS (EE/BK)   // 32
#define NTILES (NPAD/BN) // 32

// Scratch (device globals: allocation-free per harness rules)
__device__ __nv_bfloat16 g_hsb[(size_t)MPAD * EE];   // padded rows zero
__device__ __nv_bfloat16 g_Wtb[(size_t)NPAD * EE];   // W transposed [n][k], padded rows zero
__device__ float2 g_part[(size_t)MM * NTILES];       // per (row, ntile) (max, sumexp)
__device__ float g_lse[MM];
__device__ float g_lp[(size_t)MM * GG];
__device__ float g_ll[BSZ];

// ---------------------------------------------------------------------------
__device__ __forceinline__ uint32_t smem_u32(const void* p) {
    uint32_t a;
    asm("{ .reg .u64 t; cvta.to.shared.u64 t, %1; cvt.u32.u64 %0, t; }" : "=r"(a) : "l"(p));
    return a;
}
__device__ __forceinline__ void cp16(uint32_t dst, const void* src) {
    asm volatile("cp.async.cg.shared.global [%0], [%1], 16;" :: "r"(dst), "l"(src));
}
// swizzled offset for (row, 16B-chunk c) in a [128 rows x 64B] tile
__device__ __forceinline__ uint32_t swz(int row, int c) {
    return (uint32_t)(row * 64 + ((c ^ ((row >> 1) & 3)) << 4));
}

// ---------------------------------------------------------------------------
// Conversion kernels
// ---------------------------------------------------------------------------
__global__ __launch_bounds__(256)
void conv_hs_kernel(const float* __restrict__ hs) {
    size_t i = ((size_t)blockIdx.x * 256 + threadIdx.x) * 4;
    if (i >= (size_t)MPAD * EE) return;
    size_t row = i >> 10;
    float4 v = make_float4(0.f, 0.f, 0.f, 0.f);
    if (row < MM) v = *(const float4*)(hs + i);
    __nv_bfloat162* dst = (__nv_bfloat162*)(g_hsb + i);
    dst[0] = __nv_bfloat162(__float2bfloat16(v.x), __float2bfloat16(v.y));
    dst[1] = __nv_bfloat162(__float2bfloat16(v.z), __float2bfloat16(v.w));
}

__global__ __launch_bounds__(256)
void conv_W_kernel(const float* __restrict__ W) {
    __shared__ float t[32][33];
    int n0 = blockIdx.x * 32;
    int k0 = blockIdx.y * 32;
    int tx = threadIdx.x;      // 0..31
    int ty = threadIdx.y;      // 0..7
#pragma unroll
    for (int j = 0; j < 32; j += 8)
        t[ty + j][tx] = W[(size_t)(k0 + ty + j) * VV + n0 + tx];
    __syncthreads();
#pragma unroll
    for (int j = 0; j < 32; j += 8)
        g_Wtb[(size_t)(n0 + ty + j) * EE + k0 + tx] = __float2bfloat16(t[tx][ty + j]);
}

__global__ __launch_bounds__(256)
void pad_W_kernel() {
    int i = blockIdx.x * 256 + threadIdx.x;
    if (i < (NPAD - VV) * EE)
        g_Wtb[(size_t)VV * EE + i] = __float2bfloat16(0.f);
}

// ---------------------------------------------------------------------------
// GEMM (bf16 mma.sync) with fused per-tile logsumexp partial epilogue.
// A = g_hsb [MPAD][EE], B = g_Wtb [NPAD][EE] (n-major, k contiguous).
// Block 128x128, 8 warps in 2(M) x 4(N) grid, warp tile 64x32.
// ---------------------------------------------------------------------------
__global__ __launch_bounds__(256, 2)
void gemm_lse_kernel(const float* __restrict__ bias) {
    extern __shared__ char dsm[];
    __shared__ float2 red[4][BM];

    const int tid = threadIdx.x;
    const int warp = tid >> 5, lane = tid & 31;
    const int wm = (warp & 1) * 64, wn = (warp >> 1) * 32;
    const int bx = blockIdx.x, by = blockIdx.y;
    const int row0 = by * BM, col0 = bx * BN;
    const uint32_t sbase = smem_u32(dsm);   // stage s: A at s*16384, B at s*16384+8192

    const __nv_bfloat16* Ab = g_hsb + (size_t)row0 * EE;
    const __nv_bfloat16* Bb = g_Wtb + (size_t)col0 * EE;

    // per-thread cp.async assignment: row = tid/2, chunks {2*(tid&1), +1} (A and B)
    const int lrow = tid >> 1;
    const int lc0 = (tid & 1) * 2;
    const uint32_t dA0 = swz(lrow, lc0);
    const uint32_t dA1 = swz(lrow, lc0 + 1);
    const __nv_bfloat16* srcA = Ab + (size_t)lrow * EE + lc0 * 8;
    const __nv_bfloat16* srcB = Bb + (size_t)lrow * EE + lc0 * 8;

    float acc[4][4][4];
#pragma unroll
    for (int mi = 0; mi < 4; mi++)
#pragma unroll
        for (int ni = 0; ni < 4; ni++)
#pragma unroll
            for (int r = 0; r < 4; r++) acc[mi][ni][r] = 0.f;

    // ldmatrix smem offsets (stage-relative), per (mi,kk) and (ni,kk)
    uint32_t aoff[2][4], boff[2][4];
#pragma unroll
    for (int kk = 0; kk < 2; kk++) {
#pragma unroll
        for (int mi = 0; mi < 4; mi++) {
            int r = wm + mi * 16 + (lane & 15);
            int c = kk * 2 + ((lane >> 4) & 1);
            aoff[kk][mi] = sbase + swz(r, c);
        }
#pragma unroll
        for (int ni = 0; ni < 4; ni++) {
            int r = wn + ni * 8 + (lane & 7);
            int c = kk * 2 + ((lane >> 3) & 1);
            boff[kk][ni] = sbase + 8192 + swz(r, c);
        }
    }

#define LOAD_STAGE(st, kt) do { \
    uint32_t b_ = (uint32_t)(st) * 16384; \
    const __nv_bfloat16* a_ = srcA + (kt) * BK; \
    const __nv_bfloat16* w_ = srcB + (kt) * BK; \
    cp16(sbase + b_ + dA0, a_); \
    cp16(sbase + b_ + dA1, a_ + 8); \
    cp16(sbase + b_ + 8192 + dA0, w_); \
    cp16(sbase + b_ + 8192 + dA1, w_ + 8); \
    asm volatile("cp.async.commit_group;" ::: "memory"); \
} while (0)

    LOAD_STAGE(0, 0);
    LOAD_STAGE(1, 1);
    LOAD_STAGE(2, 2);

    for (int kt = 0; kt < KITERS; kt++) {
        const int st = kt & 3;
        if (kt < KITERS - 3)
            asm volatile("cp.async.wait_group 2;" ::: "memory");
        else if (kt == KITERS - 3)
            asm volatile("cp.async.wait_group 2;" ::: "memory");
        else if (kt == KITERS - 2)
            asm volatile("cp.async.wait_group 1;" ::: "memory");
        else
            asm volatile("cp.async.wait_group 0;" ::: "memory");
        __syncthreads();

        const uint32_t stb = (uint32_t)st * 16384;
#pragma unroll
        for (int kk = 0; kk < 2; kk++) {
            uint32_t af[4][4], bf[4][2];
#pragma unroll
            for (int mi = 0; mi < 4; mi++)
                asm volatile("ldmatrix.sync.aligned.m8n8.x4.shared.b16 {%0,%1,%2,%3}, [%4];"
                             : "=r"(af[mi][0]), "=r"(af[mi][1]), "=r"(af[mi][2]), "=r"(af[mi][3])
                             : "r"(aoff[kk][mi] + stb));
#pragma unroll
            for (int ni = 0; ni < 4; ni++)
                asm volatile("ldmatrix.sync.aligned.m8n8.x2.shared.b16 {%0,%1}, [%2];"
                             : "=r"(bf[ni][0]), "=r"(bf[ni][1])
                             : "r"(boff[kk][ni] + stb));
#pragma unroll
            for (int mi = 0; mi < 4; mi++)
#pragma unroll
                for (int ni = 0; ni < 4; ni++)
                    asm volatile(
                        "mma.sync.aligned.m16n8k16.row.col.f32.bf16.bf16.f32 "
                        "{%0,%1,%2,%3}, {%4,%5,%6,%7}, {%8,%9}, {%0,%1,%2,%3};"
                        : "+f"(acc[mi][ni][0]), "+f"(acc[mi][ni][1]),
                          "+f"(acc[mi][ni][2]), "+f"(acc[mi][ni][3])
                        : "r"(af[mi][0]), "r"(af[mi][1]), "r"(af[mi][2]), "r"(af[mi][3]),
                          "r"(bf[ni][0]), "r"(bf[ni][1]));
        }
        if (kt + 3 < KITERS) LOAD_STAGE((kt + 3) & 3, kt + 3);
    }

    // Fused LSE epilogue: per-row (max, sumexp) over this block's 128 cols.
#pragma unroll
    for (int mi = 0; mi < 4; mi++) {
        float m1 = NEGF, s1 = 0.f, m2 = NEGF, s2 = 0.f;
#pragma unroll
        for (int ni = 0; ni < 4; ni++) {
            int gcol = col0 + wn + ni * 8 + 2 * (lane & 3);
            float b0 = 0.f, b1 = 0.f;
            bool ok = gcol < VV;
            if (ok) { float2 bv = *(const float2*)(bias + gcol); b0 = bv.x; b1 = bv.y; }
            float v;
            v = ok ? acc[mi][ni][0] + b0 : NEGF;
            if (v > m1) { s1 = s1 * __expf(m1 - v) + 1.f; m1 = v; } else s1 += __expf(v - m1);
            v = ok ? acc[mi][ni][1] + b1 : NEGF;
            if (v > m1) { s1 = s1 * __expf(m1 - v) + 1.f; m1 = v; } else s1 += __expf(v - m1);
            v = ok ? acc[mi][ni][2] + b0 : NEGF;
            if (v > m2) { s2 = s2 * __expf(m2 - v) + 1.f; m2 = v; } else s2 += __expf(v - m2);
            v = ok ? acc[mi][ni][3] + b1 : NEGF;
            if (v > m2) { s2 = s2 * __expf(m2 - v) + 1.f; m2 = v; } else s2 += __expf(v - m2);
        }
        // quad reduce (lanes sharing the same row: xor 1, 2)
#pragma unroll
        for (int msk = 1; msk <= 2; msk <<= 1) {
            float om = __shfl_xor_sync(0xffffffffu, m1, msk);
            float os = __shfl_xor_sync(0xffffffffu, s1, msk);
            float M = fmaxf(m1, om);
            s1 = s1 * __expf(m1 - M) + os * __expf(om - M);
            m1 = M;
            om = __shfl_xor_sync(0xffffffffu, m2, msk);
            os = __shfl_xor_sync(0xffffffffu, s2, msk);
            M = fmaxf(m2, om);
            s2 = s2 * __expf(m2 - M) + os * __expf(om - M);
            m2 = M;
        }
        if ((lane & 3) == 0) {
            int r1 = wm + mi * 16 + (lane >> 2);
            red[warp >> 1][r1] = make_float2(m1, s1);
            red[warp >> 1][r1 + 8] = make_float2(m2, s2);
        }
    }
    __syncthreads();
    if (tid < BM) {
        float m = NEGF, s = 0.f;
#pragma unroll
        for (int j = 0; j < 4; j++) {
            float2 p = red[j][tid];
            float M = fmaxf(m, p.x);
            s = s * __expf(m - M) + p.y * __expf(p.x - M);
            m = M;
        }
        int grow = row0 + tid;
        if (grow < MM) g_part[(size_t)grow * NTILES + bx] = make_float2(m, s);
    }
#undef LOAD_STAGE
}

// ---------------------------------------------------------------------------
// Reduce 32 partials per row -> lse
// ---------------------------------------------------------------------------
__global__ __launch_bounds__(256)
void lse_reduce_kernel() {
    int row = blockIdx.x * 8 + (threadIdx.x >> 5);
    int lane = threadIdx.x & 31;
    float2 p = g_part[(size_t)row * NTILES + lane];
    float m = p.x, s = p.y;
#pragma unroll
    for (int msk = 16; msk > 0; msk >>= 1) {
        float om = __shfl_xor_sync(0xffffffffu, m, msk);
        float os = __shfl_xor_sync(0xffffffffu, s, msk);
        float M = fmaxf(m, om);
        s = s * __expf(m - M) + os * __expf(om - M);
        m = M;
    }
    if (lane == 0) g_lse[row] = m + logf(s);
}

// ---------------------------------------------------------------------------
// Gather: recompute only the 101 needed logits per row, subtract lse.
// ---------------------------------------------------------------------------
__global__ __launch_bounds__(128)
void gather_kernel(const int* __restrict__ ys, const float* __restrict__ bias) {
    __shared__ float a[EE];
    const int row = blockIdx.x;
    const int b = row / TT;
    const int tid = threadIdx.x;

    const __nv_bfloat16* hr = g_hsb + (size_t)row * EE;
    {
        int i = tid;   // EE/8 = 128 chunks of 8 bf16
        uint4 u = *(const uint4*)(hr + i * 8);
        const __nv_bfloat162* p2 = (const __nv_bfloat162*)&u;
#pragma unroll
        for (int j = 0; j < 4; j++) {
            float2 f = __bfloat1622float2(p2[j]);
            a[i * 8 + 2 * j] = f.x;
            a[i * 8 + 2 * j + 1] = f.y;
        }
    }
    __syncthreads();

    if (tid < GG) {
        int col = 0;
        if (tid > 0) {
            int y = ys[b * LL + tid - 1];
            col = y < 0 ? 0 : y;
        }
        const __nv_bfloat16* wr = g_Wtb + (size_t)col * EE;
        float acc = 0.f;
        for (int k = 0; k < EE; k += 8) {
            uint4 u = *(const uint4*)(wr + k);
            const __nv_bfloat162* p2 = (const __nv_bfloat162*)&u;
            float4 a0 = *(const float4*)&a[k];
            float4 a1 = *(const float4*)&a[k + 4];
            float2 w0 = __bfloat1622float2(p2[0]);
            float2 w1 = __bfloat1622float2(p2[1]);
            float2 w2 = __bfloat1622float2(p2[2]);
            float2 w3 = __bfloat1622float2(p2[3]);
            acc += a0.x * w0.x + a0.y * w0.y + a0.z * w1.x + a0.w * w1.y;
            acc += a1.x * w2.x + a1.y * w2.y + a1.z * w3.x + a1.w * w3.y;
        }
        g_lp[(size_t)row * GG + tid] = acc + bias[col] - g_lse[row];
    }
}

// ---------------------------------------------------------------------------
// CTC forward DP, one block per batch element
// ---------------------------------------------------------------------------
__global__ __launch_bounds__(256)
void ctc_dp_kernel(const int* __restrict__ ys, const int* __restrict__ ilens,
                   const int* __restrict__ olens) {
    extern __shared__ float sm[];
    float* lps = sm;                     // [TT][GG]
    float* abuf = sm + TT * GG;          // [2][256]

    const int b = blockIdx.x;
    const int tid = threadIdx.x;
    const int s = tid;

    const float* src = g_lp + (size_t)b * TT * GG;
    for (int i = tid; i < TT * GG; i += blockDim.x) lps[i] = src[i];

    int g = 0;
    bool allow = false;
    if (s < SS && (s & 1)) {
        int l = s >> 1;
        g = 1 + l;
        int yr = ys[b * LL + l];
        int y = yr < 0 ? 0 : yr;
        int ypr = -1;
        if (l > 0) {
            int yp = ys[b * LL + l - 1];
            ypr = yp < 0 ? 0 : yp;
        }
        allow = (y != 0) && (y != ypr);
    }

    float* a0 = abuf;
    float* a1 = abuf + 256;
    a0[s] = (s == 0) ? lps[0] : ((s == 1) ? lps[1] : NEGF);
    __syncthreads();

    const int ilen = ilens[b];
    for (int t = 1; t < ilen; t++) {
        if (s < SS) {
            float v1 = a0[s];
            float v2 = (s >= 1) ? a0[s - 1] : NEGF;
            float v3 = (s >= 2 && allow) ? a0[s - 2] : NEGF;
            float m = fmaxf(v1, fmaxf(v2, v3));
            float sum = expf(v1 - m) + expf(v2 - m) + expf(v3 - m);
            a1[s] = m + logf(sum) + lps[t * GG + g];
        }
        __syncthreads();
        float* tmp = a0; a0 = a1; a1 = tmp;
    }

    if (tid == 0) {
        const int olen = olens[b];
        float va = a0[2 * olen];
        float vb = a0[2 * olen - 1];
        float m = fmaxf(va, vb);
        g_ll[b] = m + logf(expf(va - m) + expf(vb - m));
    }
}

__global__ void finalize_kernel(float* __restrict__ out) {
    if (threadIdx.x == 0) {
        float sum = 0.0f;
        for (int i = 0; i < BSZ; i++) sum += g_ll[i];
        out[0] = -sum / (float)BSZ;
    }
}

// ---------------------------------------------------------------------------
extern "C" void kernel_launch(void* const* d_in, const int* in_sizes, int n_in,
                              void* d_out, int out_size) {
    const float* hs    = (const float*)d_in[0];
    const float* W     = (const float*)d_in[1];
    const float* bias  = (const float*)d_in[2];
    const int*   ys    = (const int*)d_in[3];
    const int*   ilens = (const int*)d_in[4];
    const int*   olens = (const int*)d_in[5];
    float* out = (float*)d_out;

    conv_hs_kernel<<<(MPAD * EE) / 1024, 256>>>(hs);
    conv_W_kernel<<<dim3(VV / 32, EE / 32), dim3(32, 8)>>>(W);
    pad_W_kernel<<<((NPAD - VV) * EE + 255) / 256, 256>>>();

    const int gemm_smem = NST * 16384;   // 64 KB
    cudaFuncSetAttribute(gemm_lse_kernel,
                         cudaFuncAttributeMaxDynamicSharedMemorySize, gemm_smem);
    dim3 ggrid(NPAD / BN, MPAD / BM);    // 32 x 63
    gemm_lse_kernel<<<ggrid, 256, gemm_smem>>>(bias);

    lse_reduce_kernel<<<MM / 8, 256>>>();

    gather_kernel<<<MM, 128>>>(ys, bias);

    const int dp_smem = TT * GG * sizeof(float) + 2 * 256 * sizeof(float);
    cudaFuncSetAttribute(ctc_dp_kernel,
                         cudaFuncAttributeMaxDynamicSharedMemorySize, dp_smem);
    ctc_dp_kernel<<<BSZ, 256, dp_smem>>>(ys, ilens, olens);

    finalize_kernel<<<1, 32>>>(out);
}

// round 4
// speedup vs baseline: 3.2747x; 1.3629x over previous
#include <cuda_runtime.h>
#include <cuda_bf16.h>
#include <math.h>
#include <stdint.h>

// Problem constants
#define BSZ 16
#define TT  500
#define EE  1024
#define VV  4000
#define LL  100
#define SS  201
#define GG  101
#define MM  (BSZ*TT)     // 8000
#define MPAD 8064        // 63*128
#define NPAD 4096        // 32*128
#define NEGF (-1e30f)

// GEMM tiling (4 warps, warp tile 64x64)
#define BM 128
#define BN 128
#define BK 32
#define NST 4
#define KITERS (EE/BK)   // 32
#define NTILES (NPAD/BN) // 32
#define KSPLIT 4
#define LPK (EE/KSPLIT)  // 256
#define LPKIT (LPK/BK)   // 8

// Scratch (device globals: allocation-free per harness rules)
__device__ __nv_bfloat16 g_hsb[(size_t)MPAD * EE];   // padded rows zero
__device__ __nv_bfloat16 g_Wtb[(size_t)NPAD * EE];   // W transposed [n][k], padded rows zero
__device__ __nv_bfloat16 g_Wg[(size_t)BSZ * 128 * EE]; // gathered W cols per batch
__device__ float g_bias_g[BSZ * 128];
__device__ float2 g_part[(size_t)MM * NTILES];       // per (row, ntile) (max, sumexp)
__device__ float g_lse[MM];
__device__ float g_lpp[(size_t)KSPLIT * MM * 128];   // lp-gemm K partials
__device__ float g_lp[(size_t)MM * GG];
__device__ float g_ll[BSZ];

// ---------------------------------------------------------------------------
__device__ __forceinline__ uint32_t smem_u32(const void* p) {
    uint32_t a;
    asm("{ .reg .u64 t; cvta.to.shared.u64 t, %1; cvt.u32.u64 %0, t; }" : "=r"(a) : "l"(p));
    return a;
}
__device__ __forceinline__ void cp16(uint32_t dst, const void* src) {
    asm volatile("cp.async.cg.shared.global [%0], [%1], 16;" :: "r"(dst), "l"(src));
}
// swizzled offset for (row, 16B-chunk c) in a [rows x 64B] tile
__device__ __forceinline__ uint32_t swz(int row, int c) {
    return (uint32_t)(row * 64 + ((c ^ ((row >> 1) & 3)) << 4));
}

// ---------------------------------------------------------------------------
// Conversion kernels
// ---------------------------------------------------------------------------
__global__ __launch_bounds__(256)
void conv_hs_kernel(const float* __restrict__ hs) {
    size_t i = ((size_t)blockIdx.x * 256 + threadIdx.x) * 4;
    if (i >= (size_t)MPAD * EE) return;
    size_t row = i >> 10;
    float4 v = make_float4(0.f, 0.f, 0.f, 0.f);
    if (row < MM) v = *(const float4*)(hs + i);
    __nv_bfloat162* dst = (__nv_bfloat162*)(g_hsb + i);
    dst[0] = __nv_bfloat162(__float2bfloat16(v.x), __float2bfloat16(v.y));
    dst[1] = __nv_bfloat162(__float2bfloat16(v.z), __float2bfloat16(v.w));
}

__global__ __launch_bounds__(256)
void conv_W_kernel(const float* __restrict__ W) {
    __shared__ float t[32][33];
    int n0 = blockIdx.x * 32;
    int k0 = blockIdx.y * 32;
    int tx = threadIdx.x;      // 0..31
    int ty = threadIdx.y;      // 0..7
#pragma unroll
    for (int j = 0; j < 32; j += 8)
        t[ty + j][tx] = W[(size_t)(k0 + ty + j) * VV + n0 + tx];
    __syncthreads();
#pragma unroll
    for (int j = 0; j < 32; j += 8)
        g_Wtb[(size_t)(n0 + ty + j) * EE + k0 + tx] = __float2bfloat16(t[tx][ty + j]);
}

__global__ __launch_bounds__(256)
void pad_W_kernel() {
    int i = blockIdx.x * 256 + threadIdx.x;
    if (i < (NPAD - VV) * EE)
        g_Wtb[(size_t)VV * EE + i] = __float2bfloat16(0.f);
}

// ---------------------------------------------------------------------------
// Gather per-batch label columns of W into compact [128][EE] matrices
// ---------------------------------------------------------------------------
__global__ __launch_bounds__(128)
void gather_cols_kernel(const int* __restrict__ ys, const float* __restrict__ bias) {
    const int b = blockIdx.x >> 7;
    const int s = blockIdx.x & 127;
    const int tid = threadIdx.x;
    int col = -1;
    if (s == 0) col = 0;
    else if (s < GG) {
        int y = ys[b * LL + s - 1];
        col = y < 0 ? 0 : y;
    }
    uint4 v = make_uint4(0, 0, 0, 0);
    if (col >= 0) v = *(const uint4*)(g_Wtb + (size_t)col * EE + tid * 8);
    *(uint4*)(g_Wg + ((size_t)(b * 128 + s)) * EE + tid * 8) = v;
    if (tid == 0) g_bias_g[b * 128 + s] = (col >= 0) ? bias[col] : 0.f;
}

// ---------------------------------------------------------------------------
// Main GEMM (bf16 mma.sync, 4 warps, warp tile 64x64) with fused LSE epilogue
// ---------------------------------------------------------------------------
__global__ __launch_bounds__(128, 2)
void gemm_lse_kernel(const float* __restrict__ bias) {
    extern __shared__ char dsm[];
    __shared__ float2 red[2][BM];

    const int tid = threadIdx.x;
    const int warp = tid >> 5, lane = tid & 31;
    const int wm = (warp & 1) * 64, wn = (warp >> 1) * 64;
    const int bx = blockIdx.x, by = blockIdx.y;
    const int row0 = by * BM, col0 = bx * BN;
    const uint32_t sbase = smem_u32(dsm);   // stage s: A at s*16384, B at +8192

    const __nv_bfloat16* srcA = g_hsb + ((size_t)row0 + tid) * EE;
    const __nv_bfloat16* srcB = g_Wtb + ((size_t)col0 + tid) * EE;
    uint32_t dsw[4];
#pragma unroll
    for (int c = 0; c < 4; c++) dsw[c] = swz(tid, c);

    float acc[4][8][4];
#pragma unroll
    for (int mi = 0; mi < 4; mi++)
#pragma unroll
        for (int ni = 0; ni < 8; ni++)
#pragma unroll
            for (int r = 0; r < 4; r++) acc[mi][ni][r] = 0.f;

    // ldmatrix smem offsets (stage-relative)
    uint32_t aoff[2][4], boff[2][4];
#pragma unroll
    for (int kk = 0; kk < 2; kk++) {
#pragma unroll
        for (int mi = 0; mi < 4; mi++) {
            int r = wm + mi * 16 + (lane & 15);
            int c = kk * 2 + (lane >> 4);
            aoff[kk][mi] = sbase + swz(r, c);
        }
#pragma unroll
        for (int nj = 0; nj < 4; nj++) {
            int r = wn + nj * 16 + ((lane >> 4) << 3) + (lane & 7);
            int c = kk * 2 + ((lane >> 3) & 1);
            boff[kk][nj] = sbase + 8192 + swz(r, c);
        }
    }

#define LOAD_STAGE(st, kt) do { \
    uint32_t b_ = (uint32_t)(st) * 16384; \
    const __nv_bfloat16* a_ = srcA + (kt) * BK; \
    const __nv_bfloat16* w_ = srcB + (kt) * BK; \
    cp16(sbase + b_ + dsw[0], a_); \
    cp16(sbase + b_ + dsw[1], a_ + 8); \
    cp16(sbase + b_ + dsw[2], a_ + 16); \
    cp16(sbase + b_ + dsw[3], a_ + 24); \
    cp16(sbase + b_ + 8192 + dsw[0], w_); \
    cp16(sbase + b_ + 8192 + dsw[1], w_ + 8); \
    cp16(sbase + b_ + 8192 + dsw[2], w_ + 16); \
    cp16(sbase + b_ + 8192 + dsw[3], w_ + 24); \
    asm volatile("cp.async.commit_group;" ::: "memory"); \
} while (0)

    LOAD_STAGE(0, 0);
    LOAD_STAGE(1, 1);
    LOAD_STAGE(2, 2);

    for (int kt = 0; kt < KITERS; kt++) {
        const int st = kt & 3;
        if (kt < KITERS - 2)
            asm volatile("cp.async.wait_group 2;" ::: "memory");
        else if (kt == KITERS - 2)
            asm volatile("cp.async.wait_group 1;" ::: "memory");
        else
            asm volatile("cp.async.wait_group 0;" ::: "memory");
        __syncthreads();

        const uint32_t stb = (uint32_t)st * 16384;
#pragma unroll
        for (int kk = 0; kk < 2; kk++) {
            uint32_t af[4][4], bf[4][4];
#pragma unroll
            for (int mi = 0; mi < 4; mi++)
                asm volatile("ldmatrix.sync.aligned.m8n8.x4.shared.b16 {%0,%1,%2,%3}, [%4];"
                             : "=r"(af[mi][0]), "=r"(af[mi][1]), "=r"(af[mi][2]), "=r"(af[mi][3])
                             : "r"(aoff[kk][mi] + stb));
#pragma unroll
            for (int nj = 0; nj < 4; nj++)
                asm volatile("ldmatrix.sync.aligned.m8n8.x4.shared.b16 {%0,%1,%2,%3}, [%4];"
                             : "=r"(bf[nj][0]), "=r"(bf[nj][1]), "=r"(bf[nj][2]), "=r"(bf[nj][3])
                             : "r"(boff[kk][nj] + stb));
#pragma unroll
            for (int mi = 0; mi < 4; mi++)
#pragma unroll
                for (int ni = 0; ni < 8; ni++)
                    asm volatile(
                        "mma.sync.aligned.m16n8k16.row.col.f32.bf16.bf16.f32 "
                        "{%0,%1,%2,%3}, {%4,%5,%6,%7}, {%8,%9}, {%0,%1,%2,%3};"
                        : "+f"(acc[mi][ni][0]), "+f"(acc[mi][ni][1]),
                          "+f"(acc[mi][ni][2]), "+f"(acc[mi][ni][3])
                        : "r"(af[mi][0]), "r"(af[mi][1]), "r"(af[mi][2]), "r"(af[mi][3]),
                          "r"(bf[ni >> 1][(ni & 1) * 2]), "r"(bf[ni >> 1][(ni & 1) * 2 + 1]));
        }
        if (kt + 3 < KITERS) LOAD_STAGE((kt + 3) & 3, kt + 3);
    }
#undef LOAD_STAGE

    // Fused LSE epilogue: per-row (max, sumexp) over this warp's 64 cols
#pragma unroll
    for (int mi = 0; mi < 4; mi++) {
        float m1 = NEGF, s1 = 0.f, m2 = NEGF, s2 = 0.f;
#pragma unroll
        for (int ni = 0; ni < 8; ni++) {
            int gcol = col0 + wn + ni * 8 + 2 * (lane & 3);
            float b0 = 0.f, b1 = 0.f;
            bool ok = gcol < VV;
            if (ok) { float2 bv = *(const float2*)(bias + gcol); b0 = bv.x; b1 = bv.y; }
            float v;
            v = ok ? acc[mi][ni][0] + b0 : NEGF;
            if (v > m1) { s1 = s1 * __expf(m1 - v) + 1.f; m1 = v; } else s1 += __expf(v - m1);
            v = ok ? acc[mi][ni][1] + b1 : NEGF;
            if (v > m1) { s1 = s1 * __expf(m1 - v) + 1.f; m1 = v; } else s1 += __expf(v - m1);
            v = ok ? acc[mi][ni][2] + b0 : NEGF;
            if (v > m2) { s2 = s2 * __expf(m2 - v) + 1.f; m2 = v; } else s2 += __expf(v - m2);
            v = ok ? acc[mi][ni][3] + b1 : NEGF;
            if (v > m2) { s2 = s2 * __expf(m2 - v) + 1.f; m2 = v; } else s2 += __expf(v - m2);
        }
#pragma unroll
        for (int msk = 1; msk <= 2; msk <<= 1) {
            float om = __shfl_xor_sync(0xffffffffu, m1, msk);
            float os = __shfl_xor_sync(0xffffffffu, s1, msk);
            float M = fmaxf(m1, om);
            s1 = s1 * __expf(m1 - M) + os * __expf(om - M);
            m1 = M;
            om = __shfl_xor_sync(0xffffffffu, m2, msk);
            os = __shfl_xor_sync(0xffffffffu, s2, msk);
            M = fmaxf(m2, om);
            s2 = s2 * __expf(m2 - M) + os * __expf(om - M);
            m2 = M;
        }
        if ((lane & 3) == 0) {
            int r1 = wm + mi * 16 + (lane >> 2);
            red[warp >> 1][r1] = make_float2(m1, s1);
            red[warp >> 1][r1 + 8] = make_float2(m2, s2);
        }
    }
    __syncthreads();
    {
        float2 p0 = red[0][tid];
        float2 p1 = red[1][tid];
        float M = fmaxf(p0.x, p1.x);
        float s = p0.y * __expf(p0.x - M) + p1.y * __expf(p1.x - M);
        int grow = row0 + tid;
        if (grow < MM) g_part[(size_t)grow * NTILES + bx] = make_float2(M, s);
    }
}

// ---------------------------------------------------------------------------
// lp GEMM: per batch, [<=500 x 1024] x [1024 x 128(gathered)] with K split 4.
// Same mma pipeline; writes raw partial sums to g_lpp.
// ---------------------------------------------------------------------------
__global__ __launch_bounds__(128, 2)
void lp_gemm_kernel() {
    extern __shared__ char dsm[];

    const int tid = threadIdx.x;
    const int warp = tid >> 5, lane = tid & 31;
    const int wm = (warp & 1) * 64, wn = (warp >> 1) * 64;
    const int mt = blockIdx.x;         // 0..3
    const int ks = blockIdx.y;         // 0..3
    const int b  = blockIdx.z;         // 0..15
    const int row0 = b * TT + mt * BM;
    const int kb = ks * LPK;
    const uint32_t sbase = smem_u32(dsm);

    const __nv_bfloat16* srcA = g_hsb + ((size_t)row0 + tid) * EE + kb;
    const __nv_bfloat16* srcB = g_Wg + ((size_t)(b * 128) + tid) * EE + kb;
    uint32_t dsw[4];
#pragma unroll
    for (int c = 0; c < 4; c++) dsw[c] = swz(tid, c);

    float acc[4][8][4];
#pragma unroll
    for (int mi = 0; mi < 4; mi++)
#pragma unroll
        for (int ni = 0; ni < 8; ni++)
#pragma unroll
            for (int r = 0; r < 4; r++) acc[mi][ni][r] = 0.f;

    uint32_t aoff[2][4], boff[2][4];
#pragma unroll
    for (int kk = 0; kk < 2; kk++) {
#pragma unroll
        for (int mi = 0; mi < 4; mi++) {
            int r = wm + mi * 16 + (lane & 15);
            int c = kk * 2 + (lane >> 4);
            aoff[kk][mi] = sbase + swz(r, c);
        }
#pragma unroll
        for (int nj = 0; nj < 4; nj++) {
            int r = wn + nj * 16 + ((lane >> 4) << 3) + (lane & 7);
            int c = kk * 2 + ((lane >> 3) & 1);
            boff[kk][nj] = sbase + 8192 + swz(r, c);
        }
    }

#define LOAD_STAGE(st, kt) do { \
    uint32_t b_ = (uint32_t)(st) * 16384; \
    const __nv_bfloat16* a_ = srcA + (kt) * BK; \
    const __nv_bfloat16* w_ = srcB + (kt) * BK; \
    cp16(sbase + b_ + dsw[0], a_); \
    cp16(sbase + b_ + dsw[1], a_ + 8); \
    cp16(sbase + b_ + dsw[2], a_ + 16); \
    cp16(sbase + b_ + dsw[3], a_ + 24); \
    cp16(sbase + b_ + 8192 + dsw[0], w_); \
    cp16(sbase + b_ + 8192 + dsw[1], w_ + 8); \
    cp16(sbase + b_ + 8192 + dsw[2], w_ + 16); \
    cp16(sbase + b_ + 8192 + dsw[3], w_ + 24); \
    asm volatile("cp.async.commit_group;" ::: "memory"); \
} while (0)

    LOAD_STAGE(0, 0);
    LOAD_STAGE(1, 1);
    LOAD_STAGE(2, 2);

    for (int kt = 0; kt < LPKIT; kt++) {
        const int st = kt & 3;
        if (kt < LPKIT - 2)
            asm volatile("cp.async.wait_group 2;" ::: "memory");
        else if (kt == LPKIT - 2)
            asm volatile("cp.async.wait_group 1;" ::: "memory");
        else
            asm volatile("cp.async.wait_group 0;" ::: "memory");
        __syncthreads();

        const uint32_t stb = (uint32_t)st * 16384;
#pragma unroll
        for (int kk = 0; kk < 2; kk++) {
            uint32_t af[4][4], bf[4][4];
#pragma unroll
            for (int mi = 0; mi < 4; mi++)
                asm volatile("ldmatrix.sync.aligned.m8n8.x4.shared.b16 {%0,%1,%2,%3}, [%4];"
                             : "=r"(af[mi][0]), "=r"(af[mi][1]), "=r"(af[mi][2]), "=r"(af[mi][3])
                             : "r"(aoff[kk][mi] + stb));
#pragma unroll
            for (int nj = 0; nj < 4; nj++)
                asm volatile("ldmatrix.sync.aligned.m8n8.x4.shared.b16 {%0,%1,%2,%3}, [%4];"
                             : "=r"(bf[nj][0]), "=r"(bf[nj][1]), "=r"(bf[nj][2]), "=r"(bf[nj][3])
                             : "r"(boff[kk][nj] + stb));
#pragma unroll
            for (int mi = 0; mi < 4; mi++)
#pragma unroll
                for (int ni = 0; ni < 8; ni++)
                    asm volatile(
                        "mma.sync.aligned.m16n8k16.row.col.f32.bf16.bf16.f32 "
                        "{%0,%1,%2,%3}, {%4,%5,%6,%7}, {%8,%9}, {%0,%1,%2,%3};"
                        : "+f"(acc[mi][ni][0]), "+f"(acc[mi][ni][1]),
                          "+f"(acc[mi][ni][2]), "+f"(acc[mi][ni][3])
                        : "r"(af[mi][0]), "r"(af[mi][1]), "r"(af[mi][2]), "r"(af[mi][3]),
                          "r"(bf[ni >> 1][(ni & 1) * 2]), "r"(bf[ni >> 1][(ni & 1) * 2 + 1]));
        }
        if (kt + 3 < LPKIT) LOAD_STAGE((kt + 3) & 3, kt + 3);
    }
#undef LOAD_STAGE

    // Write raw partials (rows within this batch only)
#pragma unroll
    for (int mi = 0; mi < 4; mi++) {
        int lr1 = mt * BM + wm + mi * 16 + (lane >> 2);
        int s = wn + 2 * (lane & 3);
#pragma unroll
        for (int ni = 0; ni < 8; ni++) {
            int sc = s + ni * 8;
            if (lr1 < TT) {
                int gr = b * TT + lr1;
                *(float2*)(g_lpp + ((size_t)ks * MM + gr) * 128 + sc) =
                    make_float2(acc[mi][ni][0], acc[mi][ni][1]);
            }
            if (lr1 + 8 < TT) {
                int gr = b * TT + lr1 + 8;
                *(float2*)(g_lpp + ((size_t)ks * MM + gr) * 128 + sc) =
                    make_float2(acc[mi][ni][2], acc[mi][ni][3]);
            }
        }
    }
}

// ---------------------------------------------------------------------------
// Reduce 32 LSE partials per row -> lse
// ---------------------------------------------------------------------------
__global__ __launch_bounds__(256)
void lse_reduce_kernel() {
    int row = blockIdx.x * 8 + (threadIdx.x >> 5);
    int lane = threadIdx.x & 31;
    float2 p = g_part[(size_t)row * NTILES + lane];
    float m = p.x, s = p.y;
#pragma unroll
    for (int msk = 16; msk > 0; msk >>= 1) {
        float om = __shfl_xor_sync(0xffffffffu, m, msk);
        float os = __shfl_xor_sync(0xffffffffu, s, msk);
        float M = fmaxf(m, om);
        s = s * __expf(m - M) + os * __expf(om - M);
        m = M;
    }
    if (lane == 0) g_lse[row] = m + logf(s);
}

// ---------------------------------------------------------------------------
// Combine: lp = sum_k partials + bias - lse
// ---------------------------------------------------------------------------
__global__ __launch_bounds__(128)
void combine_kernel() {
    const int row = blockIdx.x;
    const int s = threadIdx.x;
    if (s >= GG) return;
    const int b = row / TT;
    float acc = 0.f;
#pragma unroll
    for (int ks = 0; ks < KSPLIT; ks++)
        acc += g_lpp[((size_t)ks * MM + row) * 128 + s];
    g_lp[(size_t)row * GG + s] = acc + g_bias_g[b * 128 + s] - g_lse[row];
}

// ---------------------------------------------------------------------------
// CTC forward DP, one block per batch element
// ---------------------------------------------------------------------------
__global__ __launch_bounds__(256)
void ctc_dp_kernel(const int* __restrict__ ys, const int* __restrict__ ilens,
                   const int* __restrict__ olens) {
    extern __shared__ float sm[];
    float* lps = sm;                     // [TT][GG]
    float* abuf = sm + TT * GG;          // [2][256]

    const int b = blockIdx.x;
    const int tid = threadIdx.x;
    const int s = tid;

    const float* src = g_lp + (size_t)b * TT * GG;
    for (int i = tid; i < TT * GG; i += blockDim.x) lps[i] = src[i];

    int g = 0;
    bool allow = false;
    if (s < SS && (s & 1)) {
        int l = s >> 1;
        g = 1 + l;
        int yr = ys[b * LL + l];
        int y = yr < 0 ? 0 : yr;
        int ypr = -1;
        if (l > 0) {
            int yp = ys[b * LL + l - 1];
            ypr = yp < 0 ? 0 : yp;
        }
        allow = (y != 0) && (y != ypr);
    }

    float* a0 = abuf;
    float* a1 = abuf + 256;
    a0[s] = (s == 0) ? lps[0] : ((s == 1) ? lps[1] : NEGF);
    __syncthreads();

    const int ilen = ilens[b];
    for (int t = 1; t < ilen; t++) {
        if (s < SS) {
            float v1 = a0[s];
            float v2 = (s >= 1) ? a0[s - 1] : NEGF;
            float v3 = (s >= 2 && allow) ? a0[s - 2] : NEGF;
            float m = fmaxf(v1, fmaxf(v2, v3));
            float sum = __expf(v1 - m) + __expf(v2 - m) + __expf(v3 - m);
            a1[s] = m + __logf(sum) + lps[t * GG + g];
        }
        __syncthreads();
        float* tmp = a0; a0 = a1; a1 = tmp;
    }

    if (tid == 0) {
        const int olen = olens[b];
        float va = a0[2 * olen];
        float vb = a0[2 * olen - 1];
        float m = fmaxf(va, vb);
        g_ll[b] = m + logf(expf(va - m) + expf(vb - m));
    }
}

__global__ void finalize_kernel(float* __restrict__ out) {
    if (threadIdx.x == 0) {
        float sum = 0.0f;
        for (int i = 0; i < BSZ; i++) sum += g_ll[i];
        out[0] = -sum / (float)BSZ;
    }
}

// ---------------------------------------------------------------------------
extern "C" void kernel_launch(void* const* d_in, const int* in_sizes, int n_in,
                              void* d_out, int out_size) {
    const float* hs    = (const float*)d_in[0];
    const float* W     = (const float*)d_in[1];
    const float* bias  = (const float*)d_in[2];
    const int*   ys    = (const int*)d_in[3];
    const int*   ilens = (const int*)d_in[4];
    const int*   olens = (const int*)d_in[5];
    float* out = (float*)d_out;

    conv_hs_kernel<<<(MPAD * EE) / 1024, 256>>>(hs);
    conv_W_kernel<<<dim3(VV / 32, EE / 32), dim3(32, 8)>>>(W);
    pad_W_kernel<<<((NPAD - VV) * EE + 255) / 256, 256>>>();
    gather_cols_kernel<<<BSZ * 128, 128>>>(ys, bias);

    const int gemm_smem = NST * 16384;   // 64 KB
    cudaFuncSetAttribute(gemm_lse_kernel,
                         cudaFuncAttributeMaxDynamicSharedMemorySize, gemm_smem);
    dim3 ggrid(NPAD / BN, MPAD / BM);    // 32 x 63
    gemm_lse_kernel<<<ggrid, 128, gemm_smem>>>(bias);

    lse_reduce_kernel<<<MM / 8, 256>>>();

    cudaFuncSetAttribute(lp_gemm_kernel,
                         cudaFuncAttributeMaxDynamicSharedMemorySize, gemm_smem);
    lp_gemm_kernel<<<dim3(4, KSPLIT, BSZ), 128, gemm_smem>>>();

    combine_kernel<<<MM, 128>>>();

    const int dp_smem = TT * GG * sizeof(float) + 2 * 256 * sizeof(float);
    cudaFuncSetAttribute(ctc_dp_kernel,
                         cudaFuncAttributeMaxDynamicSharedMemorySize, dp_smem);
    ctc_dp_kernel<<<BSZ, 256, dp_smem>>>(ys, ilens, olens);

    finalize_kernel<<<1, 32>>>(out);
}